// round 17
// baseline (speedup 1.0000x reference)
#include <cuda_runtime.h>

#define NB     131072      // 32768 centers * 4 species
#define MAXE   1048576

namespace {

constexpr float PI_F   = 3.14159265358979323846f;
constexpr float NORM_F = 0.17677669529663687f;   // 1/sqrt(32)

typedef unsigned long long ull;

__device__ int    g_cnt[NB];
__device__ int    g_cur[NB];
__device__ int    g_off[NB];
__device__ int    g_blk[128];
__device__ float4 g_edges[MAXE];

// ---- packed fp32x2 helpers ----
__device__ __forceinline__ ull pack2(float lo, float hi) {
    ull r; asm("mov.b64 %0, {%1, %2};" : "=l"(r) : "f"(lo), "f"(hi)); return r;
}
__device__ __forceinline__ void unpack2(ull v, float& lo, float& hi) {
    asm("mov.b64 {%0, %1}, %2;" : "=f"(lo), "=f"(hi) : "l"(v));
}
__device__ __forceinline__ ull ffma2(ull a, ull b, ull c) {
    ull d; asm("fma.rn.f32x2 %0, %1, %2, %3;" : "=l"(d) : "l"(a), "l"(b), "l"(c));
    return d;
}
__device__ __forceinline__ ull addx2(ull a, ull b) {
    ull d; asm("add.rn.f32x2 %0, %1, %2;" : "=l"(d) : "l"(a), "l"(b));
    return d;
}

// ------------------------------------------------------------ histogram (2 edges/thread)
__global__ void k_hist(const int* __restrict__ cidx,
                       const int* __restrict__ sidx, int n) {
    int i = blockIdx.x * blockDim.x + threadIdx.x;
    int e = i * 2;
    if (e + 1 < n) {
        int2 c = *reinterpret_cast<const int2*>(&cidx[e]);
        int2 s = *reinterpret_cast<const int2*>(&sidx[e]);
        atomicAdd(&g_cnt[c.x * 4 + s.x], 1);
        atomicAdd(&g_cnt[c.y * 4 + s.y], 1);
    } else if (e < n) {
        atomicAdd(&g_cnt[cidx[e] * 4 + sidx[e]], 1);
    }
}

// ------------------------------------------------------------ scan step A
__global__ void k_scanA() {            // 128 blocks x 256 threads
    __shared__ int sm[256];
    int t = threadIdx.x, blk = blockIdx.x;
    int base = blk * 1024 + t * 4;
    int4 c = *reinterpret_cast<const int4*>(&g_cnt[base]);
    int s = c.x + c.y + c.z + c.w;
    sm[t] = s;
    __syncthreads();
    #pragma unroll
    for (int off = 1; off < 256; off <<= 1) {
        int v = (t >= off) ? sm[t - off] : 0;
        __syncthreads();
        sm[t] += v;
        __syncthreads();
    }
    int ex = sm[t] - s;                // exclusive within CTA
    int4 o;
    o.x = ex; o.y = ex + c.x; o.z = o.y + c.y; o.w = o.z + c.z;
    *reinterpret_cast<int4*>(&g_cur[base]) = o;
    if (t == 255) g_blk[blk] = sm[255];
}

// ------------------------------------------------------------ scan step B+C fused
__global__ void k_scanC() {            // 128 blocks x 256 threads
    __shared__ int s_wsum[8];
    __shared__ int s_off;
    int t = threadIdx.x, blk = blockIdx.x;

    int contrib = (t < 128 && t < blk) ? g_blk[t] : 0;
    #pragma unroll
    for (int o = 16; o; o >>= 1)
        contrib += __shfl_down_sync(0xffffffffu, contrib, o);
    if ((t & 31) == 0) s_wsum[t >> 5] = contrib;
    __syncthreads();
    if (t == 0) {
        int a = 0;
        #pragma unroll
        for (int i = 0; i < 8; i++) a += s_wsum[i];
        s_off = a;
    }
    __syncthreads();
    int off = s_off;

    int i = blk * 256 + t;
    int4 v = *reinterpret_cast<int4*>(&g_cur[i * 4]);
    v.x += off; v.y += off; v.z += off; v.w += off;
    *reinterpret_cast<int4*>(&g_cur[i * 4]) = v;   // running cursor (scatter)
    *reinterpret_cast<int4*>(&g_off[i * 4]) = v;   // immutable starts (accum)
}

// ------------------------------------------------------------ scatter (1 edge/thread)
__global__ void k_scatter(const float* __restrict__ vec,
                          const int* __restrict__ cidx,
                          const int* __restrict__ sidx, int n) {
    int e = blockIdx.x * blockDim.x + threadIdx.x;
    if (e >= n) return;
    int b = cidx[e] * 4 + sidx[e];
    int p = atomicAdd(&g_cur[b], 1);
    g_edges[p] = make_float4(vec[3 * e], vec[3 * e + 1], vec[3 * e + 2],
                             __int_as_float(b));
}

// ------------------------------------------------------------ accumulate
// ONE WARP OWNS 8 CONSECUTIVE BUCKETS. Lane (k = lane&15, bh = lane>>4)
// accumulates HALF the moment row: m[b] = sum_e sh[k]*phi[bh*6+b] (3 packed
// ull) — no duplicated work across nh. At bucket flush each lane contracts
// its 6 b's against W (smem) over all 8 n, a shfl_xor(16) butterfly combines
// the complementary halves, and each lane stores its 4 output floats once.
// No output atomics, no output memset.
__global__ __launch_bounds__(256)
void k_accum(const float* __restrict__ W, float* __restrict__ out, int n) {
    __shared__ __align__(16) float sW[384];
    __shared__ __align__(16) float s_phi[8][32 * 16];  // [warp][edge*16 + slot]
    __shared__ __align__(16) float s_sh[8][16 * 33];   // [warp][k*33 + edge]

    int t = threadIdx.x, w = t >> 5, lane = t & 31;
    for (int i = t; i < 384; i += 256) sW[i] = W[i];
    __syncthreads();

    int k  = lane & 15;
    int bh = lane >> 4;                    // basis half: b = bh*6 .. bh*6+5
    int l  = (k >= 9) ? 3 : ((k >= 4) ? 2 : ((k >= 1) ? 1 : 0));

    int ww = blockIdx.x * 8 + w;           // warp id, 16384 total
    int b0 = ww * 8;                       // first of 8 owned buckets
    int s0 = g_off[b0];
    int e3 = (b0 + 8 < NB) ? g_off[b0 + 8] : n;

    const float* shrow = &s_sh[w][k * 33];
    const float* wbase = &sW[l * 96 + bh * 48];   // W[l][bh*6 + bb][0..7]

    int curb = -1;
    ull m0 = 0ull, m1 = 0ull, m2 = 0ull;

    for (int base = s0; base < e3; base += 32) {
        int idx = base + lane;
        int b = -1;
        float4 v = make_float4(0.f, 0.f, 0.f, 0.f);
        if (idx < e3) { v = g_edges[idx]; b = __float_as_int(v.w); }

        // ---- stage phi + sh for own edge ----
        {
            float vx = v.x, vy = v.y, vz = v.z;
            float r2   = fmaf(vx, vx, fmaf(vy, vy, vz * vz)) + 1e-12f;
            float rinv = rsqrtf(r2);
            float r    = r2 * rinv;
            float x = vx * rinv, y = vy * rinv, z = vz * rinv;

            float a = (PI_F / 5.0f) * r;
            float sn, cs;
            __sincosf(a, &sn, &cs);
            float tt    = NORM_F * rinv;
            float two_c = 2.0f * cs;
            float phi[12];
            {
                float sm1 = 0.f, sc = sn;
                phi[0] = sc * tt;
                #pragma unroll
                for (int nn = 1; nn < 12; nn++) {
                    float s1 = fmaf(two_c, sc, -sm1);
                    sm1 = sc; sc = s1;
                    phi[nn] = sc * tt;
                }
            }
            // padded layout: half bh at float offset bh*8 within 16-float slot
            float* pp = &s_phi[w][lane * 16];
            *reinterpret_cast<float4*>(pp + 0)  = make_float4(phi[0], phi[1], phi[2],  phi[3]);
            *reinterpret_cast<float2*>(pp + 4)  = make_float2(phi[4], phi[5]);
            *reinterpret_cast<float4*>(pp + 8)  = make_float4(phi[6], phi[7], phi[8],  phi[9]);
            *reinterpret_cast<float2*>(pp + 12) = make_float2(phi[10], phi[11]);

            float x2 = x * x, y2 = y * y, z2 = z * z;
            float* sr = &s_sh[w][lane];
            sr[0  * 33] = 0.28209479177387814f;
            sr[1  * 33] = 0.4886025119029199f * y;
            sr[2  * 33] = 0.4886025119029199f * z;
            sr[3  * 33] = 0.4886025119029199f * x;
            sr[4  * 33] = 1.0925484305920792f * x * y;
            sr[5  * 33] = 1.0925484305920792f * y * z;
            sr[6  * 33] = 0.31539156525252005f * fmaf(3.0f, z2, -1.0f);
            sr[7  * 33] = 1.0925484305920792f * x * z;
            sr[8  * 33] = 0.5462742152960396f * (x2 - y2);
            sr[9  * 33] = 0.5900435899266435f * y * fmaf(3.0f, x2, -y2);
            sr[10 * 33] = 2.890611442640554f  * x * y * z;
            sr[11 * 33] = 0.4570457994644658f * y * fmaf(5.0f, z2, -1.0f);
            sr[12 * 33] = 0.3731763325901154f * z * fmaf(5.0f, z2, -3.0f);
            sr[13 * 33] = 0.4570457994644658f * x * fmaf(5.0f, z2, -1.0f);
            sr[14 * 33] = 1.445305721320277f  * z * (x2 - y2);
            sr[15 * 33] = 0.5900435899266435f * x * (x2 - y2);
        }
        __syncwarp();

        // ---- segment detection + half-moment accumulation ----
        int b_up = __shfl_up_sync(0xffffffffu, b, 1);
        bool head = (lane == 0) || (b != b_up);
        unsigned hm = __ballot_sync(0xffffffffu, head);

        unsigned msk = hm;
        while (msk) {
            int s = __ffs(msk) - 1;
            msk &= msk - 1;
            int e2 = msk ? (__ffs(msk) - 1) : 32;
            int bs = __shfl_sync(0xffffffffu, b, s);
            if (bs >= 0) {
                if (bs != curb) {
                    if (curb >= 0) {
                        // flush: contract own 6 b's over all 8 n, butterfly, store
                        float mv[6];
                        unpack2(m0, mv[0], mv[1]);
                        unpack2(m1, mv[2], mv[3]);
                        unpack2(m2, mv[4], mv[5]);
                        ull o01 = 0ull, o23 = 0ull, o45 = 0ull, o67 = 0ull;
                        #pragma unroll
                        for (int bb = 0; bb < 6; bb++) {
                            ull sp = pack2(mv[bb], mv[bb]);
                            ulonglong2 w0 = *reinterpret_cast<const ulonglong2*>(wbase + bb * 8);
                            ulonglong2 w1 = *reinterpret_cast<const ulonglong2*>(wbase + bb * 8 + 4);
                            o01 = ffma2(sp, w0.x, o01);
                            o23 = ffma2(sp, w0.y, o23);
                            o45 = ffma2(sp, w1.x, o45);
                            o67 = ffma2(sp, w1.y, o67);
                        }
                        // butterfly: exchange the n-half this lane does NOT store
                        ull sendA = bh ? o01 : o45;
                        ull sendB = bh ? o23 : o67;
                        ull keepA = bh ? o45 : o01;
                        ull keepB = bh ? o67 : o23;
                        ull recvA = __shfl_xor_sync(0xffffffffu, sendA, 16);
                        ull recvB = __shfl_xor_sync(0xffffffffu, sendB, 16);
                        ull finA = addx2(keepA, recvA);
                        ull finB = addx2(keepB, recvB);
                        float f0, f1, f2, f3;
                        unpack2(finA, f0, f1);
                        unpack2(finB, f2, f3);
                        float* p = out + ((curb >> 2) * 512 + k * 32 + (curb & 3) * 8 + bh * 4);
                        *reinterpret_cast<float4*>(p) = make_float4(f0, f1, f2, f3);
                    }
                    curb = bs;
                    m0 = 0ull; m1 = 0ull; m2 = 0ull;
                }
                for (int i = s; i < e2; i++) {
                    float sk = shrow[i];
                    ull skp = pack2(sk, sk);
                    const float* pb = &s_phi[w][i * 16 + bh * 8];
                    ulonglong2 q = *reinterpret_cast<const ulonglong2*>(pb);
                    ull q2 = *reinterpret_cast<const ull*>(pb + 4);
                    m0 = ffma2(skp, q.x, m0);
                    m1 = ffma2(skp, q.y, m1);
                    m2 = ffma2(skp, q2,  m2);
                }
            }
        }
        __syncwarp();
    }

    // final flush
    if (curb >= 0) {
        float mv[6];
        unpack2(m0, mv[0], mv[1]);
        unpack2(m1, mv[2], mv[3]);
        unpack2(m2, mv[4], mv[5]);
        ull o01 = 0ull, o23 = 0ull, o45 = 0ull, o67 = 0ull;
        #pragma unroll
        for (int bb = 0; bb < 6; bb++) {
            ull sp = pack2(mv[bb], mv[bb]);
            ulonglong2 w0 = *reinterpret_cast<const ulonglong2*>(wbase + bb * 8);
            ulonglong2 w1 = *reinterpret_cast<const ulonglong2*>(wbase + bb * 8 + 4);
            o01 = ffma2(sp, w0.x, o01);
            o23 = ffma2(sp, w0.y, o23);
            o45 = ffma2(sp, w1.x, o45);
            o67 = ffma2(sp, w1.y, o67);
        }
        ull sendA = bh ? o01 : o45;
        ull sendB = bh ? o23 : o67;
        ull keepA = bh ? o45 : o01;
        ull keepB = bh ? o67 : o23;
        ull recvA = __shfl_xor_sync(0xffffffffu, sendA, 16);
        ull recvB = __shfl_xor_sync(0xffffffffu, sendB, 16);
        ull finA = addx2(keepA, recvA);
        ull finB = addx2(keepB, recvB);
        float f0, f1, f2, f3;
        unpack2(finA, f0, f1);
        unpack2(finB, f2, f3);
        float* p = out + ((curb >> 2) * 512 + k * 32 + (curb & 3) * 8 + bh * 4);
        *reinterpret_cast<float4*>(p) = make_float4(f0, f1, f2, f3);
    } else {
        // keep shfl convergence for warps that never flushed (all-empty range)
        ull dummy = __shfl_xor_sync(0xffffffffu, 0ull, 16);
        (void)dummy;
        ull dummy2 = __shfl_xor_sync(0xffffffffu, 0ull, 16);
        (void)dummy2;
    }

    // empty buckets: write zeros exactly once (each lane its STG.128)
    bool is_empty = false;
    if (lane < 8) {
        int bkt = b0 + lane;
        int st  = g_off[bkt];
        int en  = (bkt + 1 < NB) ? g_off[bkt + 1] : n;
        is_empty = (st == en);
    }
    unsigned em = __ballot_sync(0xffffffffu, is_empty);
    while (em) {
        int j = __ffs(em) - 1;
        em &= em - 1;
        int bkt = b0 + j;
        float* p = out + ((bkt >> 2) * 512 + k * 32 + (bkt & 3) * 8 + bh * 4);
        *reinterpret_cast<float4*>(p) = make_float4(0.f, 0.f, 0.f, 0.f);
    }
}

} // namespace

extern "C" void kernel_launch(void* const* d_in, const int* in_sizes, int n_in,
                              void* d_out, int out_size)
{
    const float* vectors = (const float*)d_in[0];
    const float* W       = (const float*)d_in[1];
    const int*   cidx    = (const int*)d_in[2];
    const int*   sidx    = (const int*)d_in[3];
    float*       out     = (float*)d_out;

    int n_edges = in_sizes[2];

    static void* cnt_ptr = nullptr;
    if (!cnt_ptr) cudaGetSymbolAddress(&cnt_ptr, g_cnt);

    cudaMemsetAsync(cnt_ptr, 0, NB * sizeof(int), 0);
    k_hist<<<(n_edges / 2 + 255) / 256, 256>>>(cidx, sidx, n_edges);
    k_scanA<<<128, 256>>>();
    k_scanC<<<128, 256>>>();
    k_scatter<<<(n_edges + 255) / 256, 256>>>(vectors, cidx, sidx, n_edges);
    k_accum<<<NB / 8 / 8, 256>>>(W, out, n_edges);   // 16384 warps, 8 buckets each
}